// round 1
// baseline (speedup 1.0000x reference)
#include <cuda_runtime.h>
#include <math.h>

#define N_NODES 50000
#define N_EDGES 800000
#define NLAYERS 3
#define NF 256
#define EF 64
#define QD 128
#define H  64
#define TD 32
#define NT 64
#define EPSF 1e-15f

// ---------------- scratch (no cudaMalloc allowed) ----------------
__device__ __align__(16) float g_ht[N_NODES * H];
__device__ __align__(16) float g_msg[N_NODES * H];
__device__ __align__(16) float g_agg[N_NODES * H];
__device__ __align__(16) float g_A[N_NODES * H];
__device__ __align__(16) float g_B[N_NODES * H];
__device__ float g_ps[N_NODES];
__device__ float g_pd[N_NODES];
__device__ float g_m[N_NODES];
__device__ float g_den[N_NODES];
__device__ float g_ex[N_EDGES];
__device__ float g_q[H];
__device__ float g_temb[NT * TD];
__device__ float g_pte[NLAYERS * NT];
__device__ __align__(16) float g_teC[NT * H];
__device__ float g_qbn[H];
__device__ float g_qbe[H];

__device__ __forceinline__ float warpReduceSum(float v) {
#pragma unroll
    for (int o = 16; o; o >>= 1) v += __shfl_xor_sync(0xffffffffu, v, o);
    return v;
}

// ---------------- constants kernel (tiny) ----------------
__global__ void k_consts(const float* __restrict__ query, const float* __restrict__ Wq,
                         const float* __restrict__ bq, const float* __restrict__ edesc,
                         const float* __restrict__ Ws, const float* __restrict__ bs,
                         const float* __restrict__ attn_a, const float* __restrict__ Wns1,
                         const float* __restrict__ bns1, const float* __restrict__ Wes1,
                         const float* __restrict__ bes1, float* __restrict__ out_te) {
    int t = threadIdx.x;
    if (t < H) {
        float a = bq[t];
        for (int k = 0; k < QD; k++) a += query[k] * Wq[k * H + t];
        g_q[t] = a;
    }
    __syncthreads();
    for (int i = t; i < NT * TD; i += 256) {
        int ty = i / TD, j = i % TD;
        float a = bs[j];
        for (int k = 0; k < EF; k++) a += edesc[ty * EF + k] * Ws[k * TD + j];
        a = tanhf(a);
        g_temb[i] = a;
        out_te[i] = a;
    }
    __syncthreads();
    for (int i = t; i < NLAYERS * NT; i += 256) {
        int l = i / NT, ty = i % NT;
        float a = 0.f;
        for (int j = 0; j < TD; j++) a += g_temb[ty * TD + j] * attn_a[l * (2 * H + TD) + 2 * H + j];
        g_pte[i] = a;
    }
    for (int i = t; i < NT * H; i += 256) {
        int ty = i / H, j = i % H;
        float a = 0.f;
        for (int k = 0; k < TD; k++) a += g_temb[ty * TD + k] * Wes1[(2 * H + k) * H + j];
        g_teC[i] = a;
    }
    if (t < H) {
        float a = bns1[t];
        for (int k = 0; k < H; k++) a += g_q[k] * Wns1[(H + k) * H + t];
        g_qbn[t] = a;
        float b = bes1[t];
        for (int k = 0; k < H; k++) b += g_q[k] * Wes1[(2 * H + TD + k) * H + t];
        g_qbe[t] = b;
    }
}

// ---------------- K1: h0 = expmap0((nf@Wn+bn)*ts) ----------------
__global__ void k_node_embed(const float* __restrict__ nf, const float* __restrict__ Wn,
                             const float* __restrict__ bn, const float* __restrict__ ts_p,
                             float* __restrict__ h_out) {
    __shared__ __align__(16) float sW[64 * 64];
    int warp = threadIdx.x >> 5, lane = threadIdx.x & 31;
    int row = blockIdx.x * 8 + warp;
    bool valid = row < N_NODES;
    float acc0 = 0.f, acc1 = 0.f;
    for (int c = 0; c < 4; c++) {
        __syncthreads();
        for (int i = threadIdx.x; i < 64 * 64; i += 256) sW[i] = Wn[c * 64 * 64 + i];
        __syncthreads();
        if (valid) {
            float v0 = nf[row * NF + c * 64 + lane];
            float v1 = nf[row * NF + c * 64 + 32 + lane];
#pragma unroll
            for (int j = 0; j < 32; j++) {
                float w = __shfl_sync(0xffffffffu, v0, j);
                acc0 += w * sW[j * 64 + lane];
                acc1 += w * sW[j * 64 + lane + 32];
            }
#pragma unroll
            for (int j = 0; j < 32; j++) {
                float w = __shfl_sync(0xffffffffu, v1, j);
                acc0 += w * sW[(32 + j) * 64 + lane];
                acc1 += w * sW[(32 + j) * 64 + lane + 32];
            }
        }
    }
    if (!valid) return;
    float ts = *ts_p;
    float u0 = (acc0 + bn[lane]) * ts;
    float u1 = (acc1 + bn[lane + 32]) * ts;
    float nn = warpReduceSum(u0 * u0 + u1 * u1);
    float n = fmaxf(sqrtf(nn), EPSF);
    float f = tanhf(n) / n;
    h_out[row * H + lane] = u0 * f;
    h_out[row * H + lane + 32] = u1 * f;
}

// ---------------- K3: ht=logmap0(h), p_src/p_dst, init m/den/agg ----------------
__global__ void k_prep(const float* __restrict__ h, const float* __restrict__ aL) {
    __shared__ float sA[2 * H];
    if (threadIdx.x < 2 * H) sA[threadIdx.x] = aL[threadIdx.x];
    __syncthreads();
    int warp = threadIdx.x >> 5, lane = threadIdx.x & 31;
    int row = blockIdx.x * 8 + warp;
    if (row >= N_NODES) return;
    float v0 = h[row * H + lane], v1 = h[row * H + lane + 32];
    float nn = warpReduceSum(v0 * v0 + v1 * v1);
    float n = fmaxf(sqrtf(nn), EPSF);
    float p = fminf(n, 1.f - 1e-5f);
    float f = atanhf(p) / n;
    float t0 = v0 * f, t1 = v1 * f;
    g_ht[row * H + lane] = t0;
    g_ht[row * H + lane + 32] = t1;
    float ps = warpReduceSum(t0 * sA[lane] + t1 * sA[lane + 32]);
    float pd = warpReduceSum(t0 * sA[H + lane] + t1 * sA[H + lane + 32]);
    if (lane == 0) {
        g_ps[row] = ps;
        g_pd[row] = pd;
        g_m[row] = -INFINITY;
        g_den[row] = 0.f;
    }
    g_agg[row * H + lane] = 0.f;
    g_agg[row * H + lane + 32] = 0.f;
}

// ---------------- K4: edge attention score + segment max ----------------
__global__ void k_edge_max(const int* __restrict__ src, const int* __restrict__ dst,
                           const int* __restrict__ et, int l) {
    __shared__ float sp[NT];
    if (threadIdx.x < NT) sp[threadIdx.x] = g_pte[l * NT + threadIdx.x];
    __syncthreads();
    int e = blockIdx.x * 256 + threadIdx.x;
    if (e >= N_EDGES) return;
    float s = g_ps[src[e]] + g_pd[dst[e]] + sp[et[e]];
    s = s > 0.f ? s : 0.2f * s;
    g_ex[e] = s;
    float* m = &g_m[dst[e]];
    if (s >= 0.f) atomicMax((int*)m, __float_as_int(s));
    else atomicMin((unsigned int*)m, __float_as_uint(s));
}

// ---------------- K5: exp + segment sum ----------------
__global__ void k_edge_exp(const int* __restrict__ dst) {
    int e = blockIdx.x * 256 + threadIdx.x;
    if (e >= N_EDGES) return;
    int d = dst[e];
    float ex = expf(g_ex[e] - g_m[d]);
    g_ex[e] = ex;
    atomicAdd(&g_den[d], ex);
}

// ---------------- K6: msg = ht @ Wmp[l] + bmp[l] ----------------
__global__ void k_msg(const float* __restrict__ Wl, const float* __restrict__ bl) {
    __shared__ __align__(16) float sW[64 * 64];
    __shared__ float sb[H];
    for (int i = threadIdx.x; i < 64 * 64; i += 256) sW[i] = Wl[i];
    if (threadIdx.x < H) sb[threadIdx.x] = bl[threadIdx.x];
    __syncthreads();
    int warp = threadIdx.x >> 5, lane = threadIdx.x & 31;
    int row = blockIdx.x * 8 + warp;
    if (row >= N_NODES) return;
    float v0 = g_ht[row * H + lane], v1 = g_ht[row * H + lane + 32];
    float acc0 = 0.f, acc1 = 0.f;
#pragma unroll
    for (int j = 0; j < 32; j++) {
        float w = __shfl_sync(0xffffffffu, v0, j);
        acc0 += w * sW[j * 64 + lane];
        acc1 += w * sW[j * 64 + lane + 32];
    }
#pragma unroll
    for (int j = 0; j < 32; j++) {
        float w = __shfl_sync(0xffffffffu, v1, j);
        acc0 += w * sW[(32 + j) * 64 + lane];
        acc1 += w * sW[(32 + j) * 64 + lane + 32];
    }
    g_msg[row * H + lane] = acc0 + sb[lane];
    g_msg[row * H + lane + 32] = acc1 + sb[lane + 32];
}

// ---------------- K7: agg[dst] += alpha * msg[src]  (16 threads/edge, v4 red) ----------------
__global__ void k_scatter(const int* __restrict__ src, const int* __restrict__ dst) {
    int g = threadIdx.x >> 4, sub = threadIdx.x & 15;
    int e = blockIdx.x * 16 + g;
    if (e >= N_EDGES) return;
    int s_ = src[e], d_ = dst[e];
    float alpha = g_ex[e] / (g_den[d_] + EPSF);
    float4 v = ((const float4*)(g_msg + (size_t)s_ * H))[sub];
    float* p = g_agg + (size_t)d_ * H + sub * 4;
    asm volatile("red.global.add.v4.f32 [%0], {%1, %2, %3, %4};"
                 :: "l"(p), "f"(v.x * alpha), "f"(v.y * alpha),
                    "f"(v.z * alpha), "f"(v.w * alpha)
                 : "memory");
}

// ---------------- K8: h = expmap0(relu(agg)) ----------------
__global__ void k_expmap(float* __restrict__ h) {
    int warp = threadIdx.x >> 5, lane = threadIdx.x & 31;
    int row = blockIdx.x * 8 + warp;
    if (row >= N_NODES) return;
    float a0 = fmaxf(g_agg[row * H + lane], 0.f);
    float a1 = fmaxf(g_agg[row * H + lane + 32], 0.f);
    float nn = warpReduceSum(a0 * a0 + a1 * a1);
    float n = fmaxf(sqrtf(nn), EPSF);
    float f = tanhf(n) / n;
    h[row * H + lane] = a0 * f;
    h[row * H + lane + 32] = a1 * f;
}

// ---------------- K9: h_flat=logmap0(h); node scores; A,B for edge MLP ----------------
__global__ void k_final_node(const float* __restrict__ h, const float* __restrict__ Wns1,
                             const float* __restrict__ Wns2, const float* __restrict__ bns2,
                             const float* __restrict__ Wes1, float* __restrict__ out_ns) {
    __shared__ __align__(16) float sW[64 * 64];
    __shared__ float sW2[H];
    __shared__ float sqb[H];
    if (threadIdx.x < H) {
        sW2[threadIdx.x] = Wns2[threadIdx.x];
        sqb[threadIdx.x] = g_qbn[threadIdx.x];
    }
    int warp = threadIdx.x >> 5, lane = threadIdx.x & 31;
    int row = blockIdx.x * 8 + warp;
    bool valid = row < N_NODES;
    float t0 = 0.f, t1 = 0.f;
    if (valid) {
        float v0 = h[row * H + lane], v1 = h[row * H + lane + 32];
        float nn = warpReduceSum(v0 * v0 + v1 * v1);
        float n = fmaxf(sqrtf(nn), EPSF);
        float p = fminf(n, 1.f - 1e-5f);
        float f = atanhf(p) / n;
        t0 = v0 * f;
        t1 = v1 * f;
    }
    float acc0[3] = {0.f, 0.f, 0.f}, acc1[3] = {0.f, 0.f, 0.f};
#pragma unroll
    for (int ph = 0; ph < 3; ph++) {
        const float* W = (ph == 0) ? Wns1 : ((ph == 1) ? Wes1 : (Wes1 + 64 * 64));
        __syncthreads();
        for (int i = threadIdx.x; i < 64 * 64; i += 256) sW[i] = W[i];
        __syncthreads();
        float a0 = 0.f, a1 = 0.f;
#pragma unroll
        for (int j = 0; j < 32; j++) {
            float w = __shfl_sync(0xffffffffu, t0, j);
            a0 += w * sW[j * 64 + lane];
            a1 += w * sW[j * 64 + lane + 32];
        }
#pragma unroll
        for (int j = 0; j < 32; j++) {
            float w = __shfl_sync(0xffffffffu, t1, j);
            a0 += w * sW[(32 + j) * 64 + lane];
            a1 += w * sW[(32 + j) * 64 + lane + 32];
        }
        acc0[ph] = a0;
        acc1[ph] = a1;
    }
    if (!valid) return;
    float hn0 = fmaxf(acc0[0] + sqb[lane], 0.f);
    float hn1 = fmaxf(acc1[0] + sqb[lane + 32], 0.f);
    float part = warpReduceSum(hn0 * sW2[lane] + hn1 * sW2[lane + 32]);
    if (lane == 0) {
        float lg = part + bns2[0];
        out_ns[row] = 1.f / (1.f + expf(-lg));
    }
    g_A[row * H + lane] = acc0[1];
    g_A[row * H + lane + 32] = acc1[1];
    g_B[row * H + lane] = acc0[2];
    g_B[row * H + lane + 32] = acc1[2];
}

// ---------------- K10: edge scores ----------------
__global__ void k_final_edge(const int* __restrict__ src, const int* __restrict__ dst,
                             const int* __restrict__ et, const float* __restrict__ Wes2,
                             const float* __restrict__ bes2, float* __restrict__ out_es) {
    __shared__ __align__(16) float sC[NT * H];
    __shared__ __align__(16) float sqb[H];
    __shared__ __align__(16) float sW2[H];
    for (int i = threadIdx.x; i < NT * H; i += 256) sC[i] = g_teC[i];
    if (threadIdx.x < H) {
        sqb[threadIdx.x] = g_qbe[threadIdx.x];
        sW2[threadIdx.x] = Wes2[threadIdx.x];
    }
    __syncthreads();
    int g = threadIdx.x >> 4, sub = threadIdx.x & 15;
    int e = blockIdx.x * 16 + g;
    if (e >= N_EDGES) return;
    int s_ = src[e], d_ = dst[e], t_ = et[e];
    float4 a = ((const float4*)(g_A + (size_t)s_ * H))[sub];
    float4 b = ((const float4*)(g_B + (size_t)d_ * H))[sub];
    float4 c = ((const float4*)(sC + t_ * H))[sub];
    float4 q = ((const float4*)sqb)[sub];
    float h0 = fmaxf(a.x + b.x + c.x + q.x, 0.f);
    float h1 = fmaxf(a.y + b.y + c.y + q.y, 0.f);
    float h2 = fmaxf(a.z + b.z + c.z + q.z, 0.f);
    float h3 = fmaxf(a.w + b.w + c.w + q.w, 0.f);
    float4 w = ((const float4*)sW2)[sub];
    float part = h0 * w.x + h1 * w.y + h2 * w.z + h3 * w.w;
#pragma unroll
    for (int o = 8; o; o >>= 1) part += __shfl_down_sync(0xffffffffu, part, o, 16);
    if (sub == 0) {
        float lg = part + bes2[0];
        out_es[e] = 1.f / (1.f + expf(-lg));
    }
}

// ---------------- launch ----------------
extern "C" void kernel_launch(void* const* d_in, const int* in_sizes, int n_in,
                              void* d_out, int out_size) {
    const float* nf    = (const float*)d_in[0];
    const float* edesc = (const float*)d_in[1];
    const float* query = (const float*)d_in[2];
    const float* Wn    = (const float*)d_in[3];
    const float* bn    = (const float*)d_in[4];
    const float* ts    = (const float*)d_in[5];
    const float* Wq    = (const float*)d_in[6];
    const float* bq    = (const float*)d_in[7];
    const float* Ws    = (const float*)d_in[8];
    const float* bs    = (const float*)d_in[9];
    const float* attn  = (const float*)d_in[10];
    const float* Wmp   = (const float*)d_in[11];
    const float* bmp   = (const float*)d_in[12];
    const float* Wns1  = (const float*)d_in[13];
    const float* bns1  = (const float*)d_in[14];
    const float* Wns2  = (const float*)d_in[15];
    const float* bns2  = (const float*)d_in[16];
    const float* Wes1  = (const float*)d_in[17];
    const float* bes1  = (const float*)d_in[18];
    const float* Wes2  = (const float*)d_in[19];
    const float* bes2  = (const float*)d_in[20];
    const int* eidx    = (const int*)d_in[21];
    const int* etype   = (const int*)d_in[22];
    const int* src = eidx;
    const int* dst = eidx + N_EDGES;

    float* out_ns = (float*)d_out;
    float* out_es = out_ns + N_NODES;
    float* out_h  = out_es + N_EDGES;
    float* out_te = out_h + (size_t)N_NODES * H;

    const int NODE_BLOCKS = (N_NODES + 7) / 8;       // 6250
    const int EDGE_BLOCKS = (N_EDGES + 255) / 256;   // 3125
    const int EDGE_G16    = (N_EDGES + 15) / 16;     // 50000

    k_consts<<<1, 256>>>(query, Wq, bq, edesc, Ws, bs, attn, Wns1, bns1, Wes1, bes1, out_te);
    k_node_embed<<<NODE_BLOCKS, 256>>>(nf, Wn, bn, ts, out_h);
    for (int l = 0; l < NLAYERS; l++) {
        k_prep<<<NODE_BLOCKS, 256>>>(out_h, attn + l * (2 * H + TD));
        k_edge_max<<<EDGE_BLOCKS, 256>>>(src, dst, etype, l);
        k_edge_exp<<<EDGE_BLOCKS, 256>>>(dst);
        k_msg<<<NODE_BLOCKS, 256>>>(Wmp + l * H * H, bmp + l * H);
        k_scatter<<<EDGE_G16, 256>>>(src, dst);
        k_expmap<<<NODE_BLOCKS, 256>>>(out_h);
    }
    k_final_node<<<NODE_BLOCKS, 256>>>(out_h, Wns1, Wns2, bns2, Wes1, out_ns);
    k_final_edge<<<EDGE_G16, 256>>>(src, dst, etype, Wes2, bes2, out_es);
}

// round 2
// speedup vs baseline: 1.0727x; 1.0727x over previous
#include <cuda_runtime.h>
#include <math.h>

#define N_NODES 50000
#define N_EDGES 800000
#define NLAYERS 3
#define NF 256
#define EF 64
#define QD 128
#define H  64
#define TD 32
#define NT 64
#define EPSF 1e-15f

// ---------------- scratch (no cudaMalloc allowed) ----------------
__device__ __align__(16) float g_msg[N_NODES * H];
__device__ __align__(16) float g_agg[N_NODES * H];
__device__ __align__(16) float g_A[N_NODES * H];
__device__ __align__(16) float g_B[N_NODES * H];
__device__ float g_ps[N_NODES];
__device__ float g_pd[N_NODES];
__device__ float g_ex[N_EDGES];          // spill scratch for high-degree nodes
__device__ float g_q[H];
__device__ float g_temb[NT * TD];
__device__ float g_pte[NLAYERS * NT];
__device__ __align__(16) float g_teC[NT * H];
__device__ float g_qbn[H];
__device__ float g_qbe[H];
// CSR
__device__ int g_cnt[N_NODES];
__device__ int g_fill[N_NODES];
__device__ int g_rowptr[N_NODES + 1];
__device__ unsigned int g_pack[N_EDGES]; // src (16 bits) | type<<16

__device__ __forceinline__ float warpReduceSum(float v) {
#pragma unroll
    for (int o = 16; o; o >>= 1) v += __shfl_xor_sync(0xffffffffu, v, o);
    return v;
}

// ---------------- constants kernel (tiny) ----------------
__global__ void k_consts(const float* __restrict__ query, const float* __restrict__ Wq,
                         const float* __restrict__ bq, const float* __restrict__ edesc,
                         const float* __restrict__ Ws, const float* __restrict__ bs,
                         const float* __restrict__ attn_a, const float* __restrict__ Wns1,
                         const float* __restrict__ bns1, const float* __restrict__ Wes1,
                         const float* __restrict__ bes1, float* __restrict__ out_te) {
    int t = threadIdx.x;
    if (t < H) {
        float a = bq[t];
        for (int k = 0; k < QD; k++) a += query[k] * Wq[k * H + t];
        g_q[t] = a;
    }
    __syncthreads();
    for (int i = t; i < NT * TD; i += 256) {
        int ty = i / TD, j = i % TD;
        float a = bs[j];
        for (int k = 0; k < EF; k++) a += edesc[ty * EF + k] * Ws[k * TD + j];
        a = tanhf(a);
        g_temb[i] = a;
        out_te[i] = a;
    }
    __syncthreads();
    for (int i = t; i < NLAYERS * NT; i += 256) {
        int l = i / NT, ty = i % NT;
        float a = 0.f;
        for (int j = 0; j < TD; j++) a += g_temb[ty * TD + j] * attn_a[l * (2 * H + TD) + 2 * H + j];
        g_pte[i] = a;
    }
    for (int i = t; i < NT * H; i += 256) {
        int ty = i / H, j = i % H;
        float a = 0.f;
        for (int k = 0; k < TD; k++) a += g_temb[ty * TD + k] * Wes1[(2 * H + k) * H + j];
        g_teC[i] = a;
    }
    if (t < H) {
        float a = bns1[t];
        for (int k = 0; k < H; k++) a += g_q[k] * Wns1[(H + k) * H + t];
        g_qbn[t] = a;
        float b = bes1[t];
        for (int k = 0; k < H; k++) b += g_q[k] * Wes1[(2 * H + TD + k) * H + t];
        g_qbe[t] = b;
    }
}

// ---------------- CSR build ----------------
__global__ void k_zero() {
    int i = blockIdx.x * 256 + threadIdx.x;
    if (i < N_NODES) { g_cnt[i] = 0; g_fill[i] = 0; }
}
__global__ void k_hist(const int* __restrict__ dst) {
    int e = blockIdx.x * 256 + threadIdx.x;
    if (e < N_EDGES) atomicAdd(&g_cnt[dst[e]], 1);
}
__global__ void k_scan() {
    __shared__ int warp_sums[32];
    __shared__ int sbase;
    int tid = threadIdx.x, lane = tid & 31, wid = tid >> 5;
    if (tid == 0) sbase = 0;
    __syncthreads();
    for (int base = 0; base < N_NODES; base += 1024) {
        int i = base + tid;
        int v = (i < N_NODES) ? g_cnt[i] : 0;
        int x = v;
#pragma unroll
        for (int o = 1; o < 32; o <<= 1) {
            int t = __shfl_up_sync(0xffffffffu, x, o);
            if (lane >= o) x += t;
        }
        if (lane == 31) warp_sums[wid] = x;
        __syncthreads();
        if (wid == 0) {
            int w = warp_sums[lane];
#pragma unroll
            for (int o = 1; o < 32; o <<= 1) {
                int t = __shfl_up_sync(0xffffffffu, w, o);
                if (lane >= o) w += t;
            }
            warp_sums[lane] = w;
        }
        __syncthreads();
        int incl = x + (wid > 0 ? warp_sums[wid - 1] : 0) + sbase;
        if (i < N_NODES) g_rowptr[i + 1] = incl;
        __syncthreads();
        if (tid == 1023) sbase = incl;
        __syncthreads();
    }
    if (tid == 0) g_rowptr[0] = 0;
}
__global__ void k_fill(const int* __restrict__ src, const int* __restrict__ dst,
                       const int* __restrict__ et) {
    int e = blockIdx.x * 256 + threadIdx.x;
    if (e >= N_EDGES) return;
    int d = dst[e];
    int pos = g_rowptr[d] + atomicAdd(&g_fill[d], 1);
    g_pack[pos] = (unsigned int)src[e] | ((unsigned int)et[e] << 16);
}

// ---------------- per-node prep: ps, pd, msg from tangent vector ----------------
__device__ __forceinline__ void prep_from_ht(float t0, float t1, int row, int lane,
                                             const float* __restrict__ sA,
                                             const float* __restrict__ sW,
                                             const float* __restrict__ sb) {
    float ps = warpReduceSum(t0 * sA[lane] + t1 * sA[lane + 32]);
    float pd = warpReduceSum(t0 * sA[H + lane] + t1 * sA[H + lane + 32]);
    if (lane == 0) { g_ps[row] = ps; g_pd[row] = pd; }
    float acc0 = 0.f, acc1 = 0.f;
#pragma unroll
    for (int j = 0; j < 32; j++) {
        float w = __shfl_sync(0xffffffffu, t0, j);
        acc0 += w * sW[j * 64 + lane];
        acc1 += w * sW[j * 64 + lane + 32];
    }
#pragma unroll
    for (int j = 0; j < 32; j++) {
        float w = __shfl_sync(0xffffffffu, t1, j);
        acc0 += w * sW[(32 + j) * 64 + lane];
        acc1 += w * sW[(32 + j) * 64 + lane + 32];
    }
    g_msg[row * H + lane] = acc0 + sb[lane];
    g_msg[row * H + lane + 32] = acc1 + sb[lane + 32];
}

// ---------------- K1: embed + layer0 prep ----------------
__global__ void k_embed_prep(const float* __restrict__ nf, const float* __restrict__ Wn,
                             const float* __restrict__ bn, const float* __restrict__ ts_p,
                             const float* __restrict__ attn0, const float* __restrict__ Wmp0,
                             const float* __restrict__ bmp0, float* __restrict__ h_out) {
    __shared__ __align__(16) float sW[64 * 64];
    __shared__ float sA[2 * H];
    __shared__ float sb[H];
    int warp = threadIdx.x >> 5, lane = threadIdx.x & 31;
    int row = blockIdx.x * 8 + warp;
    bool valid = row < N_NODES;
    float acc0 = 0.f, acc1 = 0.f;
    for (int c = 0; c < 4; c++) {
        __syncthreads();
        for (int i = threadIdx.x; i < 64 * 64; i += 256) sW[i] = Wn[c * 64 * 64 + i];
        __syncthreads();
        if (valid) {
            float v0 = nf[row * NF + c * 64 + lane];
            float v1 = nf[row * NF + c * 64 + 32 + lane];
#pragma unroll
            for (int j = 0; j < 32; j++) {
                float w = __shfl_sync(0xffffffffu, v0, j);
                acc0 += w * sW[j * 64 + lane];
                acc1 += w * sW[j * 64 + lane + 32];
            }
#pragma unroll
            for (int j = 0; j < 32; j++) {
                float w = __shfl_sync(0xffffffffu, v1, j);
                acc0 += w * sW[(32 + j) * 64 + lane];
                acc1 += w * sW[(32 + j) * 64 + lane + 32];
            }
        }
    }
    // reload smem with Wmp[0], attn row 0, bias
    __syncthreads();
    for (int i = threadIdx.x; i < 64 * 64; i += 256) sW[i] = Wmp0[i];
    if (threadIdx.x < 2 * H) sA[threadIdx.x] = attn0[threadIdx.x];
    if (threadIdx.x < H) sb[threadIdx.x] = bmp0[threadIdx.x];
    __syncthreads();
    if (!valid) return;
    float ts = *ts_p;
    float u0 = (acc0 + bn[lane]) * ts;
    float u1 = (acc1 + bn[lane + 32]) * ts;
    float nn = warpReduceSum(u0 * u0 + u1 * u1);
    float n = fmaxf(sqrtf(nn), EPSF);
    float f = tanhf(n) / n;
    float h0 = u0 * f, h1 = u1 * f;
    h_out[row * H + lane] = h0;
    h_out[row * H + lane + 32] = h1;
    // logmap0
    float nn2 = warpReduceSum(h0 * h0 + h1 * h1);
    float n2 = fmaxf(sqrtf(nn2), EPSF);
    float p = fminf(n2, 1.f - 1e-5f);
    float f2 = atanhf(p) / n2;
    prep_from_ht(h0 * f2, h1 * f2, row, lane, sA, sW, sb);
}

// ---------------- layer edge kernel: fused max/softmax/aggregate (no atomics) ----------------
__global__ void k_layer_edge(int l) {
    __shared__ float spte[NT];
    if (threadIdx.x < NT) spte[threadIdx.x] = g_pte[l * NT + threadIdx.x];
    __syncthreads();
    int warp = threadIdx.x >> 5, lane = threadIdx.x & 31;
    int d = blockIdx.x * 8 + warp;
    if (d >= N_NODES) return;
    int row0 = g_rowptr[d];
    int deg = g_rowptr[d + 1] - row0;
    float acc0 = 0.f, acc1 = 0.f;
    if (deg > 0) {
        float pdv = g_pd[d];
        float s0 = 0.f, s1 = 0.f, s2 = 0.f, s3 = 0.f;
        float smax = -1e30f;
        for (int i = lane, c = 0; i < deg; i += 32, c++) {
            unsigned int p = g_pack[row0 + i];
            float s = g_ps[p & 0xffffu] + pdv + spte[p >> 16];
            s = s > 0.f ? s : 0.2f * s;
            if (c == 0) s0 = s; else if (c == 1) s1 = s;
            else if (c == 2) s2 = s; else if (c == 3) s3 = s;
            else g_ex[row0 + i] = s;
            smax = fmaxf(smax, s);
        }
#pragma unroll
        for (int o = 16; o; o >>= 1) smax = fmaxf(smax, __shfl_xor_sync(0xffffffffu, smax, o));
        float den = 0.f;
        for (int i = lane, c = 0; i < deg; i += 32, c++) {
            float s = (c == 0) ? s0 : (c == 1) ? s1 : (c == 2) ? s2 : (c == 3) ? s3 : g_ex[row0 + i];
            float ex = expf(s - smax);
            if (c == 0) s0 = ex; else if (c == 1) s1 = ex;
            else if (c == 2) s2 = ex; else if (c == 3) s3 = ex;
            else g_ex[row0 + i] = ex;
            den += ex;
        }
        den = warpReduceSum(den);
        float inv = 1.f / (den + EPSF);
#pragma unroll 2
        for (int j = 0; j < deg; j++) {
            int owner = j & 31, c = j >> 5;
            float ex;
            if (c < 4) {
                float v = (c == 0) ? s0 : (c == 1) ? s1 : (c == 2) ? s2 : s3;
                ex = __shfl_sync(0xffffffffu, v, owner);
            } else {
                ex = g_ex[row0 + j];
            }
            unsigned int p = g_pack[row0 + j];
            int sn = p & 0xffffu;
            float w = ex * inv;
            acc0 += w * g_msg[sn * H + lane];
            acc1 += w * g_msg[sn * H + lane + 32];
        }
    }
    g_agg[d * H + lane] = acc0;
    g_agg[d * H + lane + 32] = acc1;
}

// ---------------- node update: h=expmap(relu(agg)); prep next layer ----------------
__global__ void k_node_update(const float* __restrict__ attnL, const float* __restrict__ WmpL,
                              const float* __restrict__ bmpL, float* __restrict__ h_out) {
    __shared__ __align__(16) float sW[64 * 64];
    __shared__ float sA[2 * H];
    __shared__ float sb[H];
    for (int i = threadIdx.x; i < 64 * 64; i += 256) sW[i] = WmpL[i];
    if (threadIdx.x < 2 * H) sA[threadIdx.x] = attnL[threadIdx.x];
    if (threadIdx.x < H) sb[threadIdx.x] = bmpL[threadIdx.x];
    __syncthreads();
    int warp = threadIdx.x >> 5, lane = threadIdx.x & 31;
    int row = blockIdx.x * 8 + warp;
    if (row >= N_NODES) return;
    float a0 = fmaxf(g_agg[row * H + lane], 0.f);
    float a1 = fmaxf(g_agg[row * H + lane + 32], 0.f);
    float nn = warpReduceSum(a0 * a0 + a1 * a1);
    float n = fmaxf(sqrtf(nn), EPSF);
    float f = tanhf(n) / n;
    float h0 = a0 * f, h1 = a1 * f;
    h_out[row * H + lane] = h0;
    h_out[row * H + lane + 32] = h1;
    float nn2 = warpReduceSum(h0 * h0 + h1 * h1);
    float n2 = fmaxf(sqrtf(nn2), EPSF);
    float p = fminf(n2, 1.f - 1e-5f);
    float f2 = atanhf(p) / n2;
    prep_from_ht(h0 * f2, h1 * f2, row, lane, sA, sW, sb);
}

// ---------------- final node: h, h_flat, node scores, A/B for edge MLP ----------------
__global__ void k_final_node(const float* __restrict__ Wns1, const float* __restrict__ Wns2,
                             const float* __restrict__ bns2, const float* __restrict__ Wes1,
                             float* __restrict__ h_out, float* __restrict__ out_ns) {
    __shared__ __align__(16) float sW[64 * 64];
    __shared__ float sW2[H];
    __shared__ float sqb[H];
    if (threadIdx.x < H) {
        sW2[threadIdx.x] = Wns2[threadIdx.x];
        sqb[threadIdx.x] = g_qbn[threadIdx.x];
    }
    int warp = threadIdx.x >> 5, lane = threadIdx.x & 31;
    int row = blockIdx.x * 8 + warp;
    bool valid = row < N_NODES;
    float t0 = 0.f, t1 = 0.f;
    if (valid) {
        float a0 = fmaxf(g_agg[row * H + lane], 0.f);
        float a1 = fmaxf(g_agg[row * H + lane + 32], 0.f);
        float nn = warpReduceSum(a0 * a0 + a1 * a1);
        float n = fmaxf(sqrtf(nn), EPSF);
        float f = tanhf(n) / n;
        float h0 = a0 * f, h1 = a1 * f;
        h_out[row * H + lane] = h0;
        h_out[row * H + lane + 32] = h1;
        float nn2 = warpReduceSum(h0 * h0 + h1 * h1);
        float n2 = fmaxf(sqrtf(nn2), EPSF);
        float p = fminf(n2, 1.f - 1e-5f);
        float f2 = atanhf(p) / n2;
        t0 = h0 * f2;
        t1 = h1 * f2;
    }
    float acc0[3] = {0.f, 0.f, 0.f}, acc1[3] = {0.f, 0.f, 0.f};
#pragma unroll
    for (int ph = 0; ph < 3; ph++) {
        const float* W = (ph == 0) ? Wns1 : ((ph == 1) ? Wes1 : (Wes1 + 64 * 64));
        __syncthreads();
        for (int i = threadIdx.x; i < 64 * 64; i += 256) sW[i] = W[i];
        __syncthreads();
        float a0 = 0.f, a1 = 0.f;
#pragma unroll
        for (int j = 0; j < 32; j++) {
            float w = __shfl_sync(0xffffffffu, t0, j);
            a0 += w * sW[j * 64 + lane];
            a1 += w * sW[j * 64 + lane + 32];
        }
#pragma unroll
        for (int j = 0; j < 32; j++) {
            float w = __shfl_sync(0xffffffffu, t1, j);
            a0 += w * sW[(32 + j) * 64 + lane];
            a1 += w * sW[(32 + j) * 64 + lane + 32];
        }
        acc0[ph] = a0;
        acc1[ph] = a1;
    }
    if (!valid) return;
    float hn0 = fmaxf(acc0[0] + sqb[lane], 0.f);
    float hn1 = fmaxf(acc1[0] + sqb[lane + 32], 0.f);
    float part = warpReduceSum(hn0 * sW2[lane] + hn1 * sW2[lane + 32]);
    if (lane == 0) {
        float lg = part + bns2[0];
        out_ns[row] = 1.f / (1.f + expf(-lg));
    }
    g_A[row * H + lane] = acc0[1];
    g_A[row * H + lane + 32] = acc1[1];
    g_B[row * H + lane] = acc0[2];
    g_B[row * H + lane + 32] = acc1[2];
}

// ---------------- final edge scores ----------------
__global__ void k_final_edge(const int* __restrict__ src, const int* __restrict__ dst,
                             const int* __restrict__ et, const float* __restrict__ Wes2,
                             const float* __restrict__ bes2, float* __restrict__ out_es) {
    __shared__ __align__(16) float sC[NT * H];
    __shared__ __align__(16) float sqb[H];
    __shared__ __align__(16) float sW2[H];
    for (int i = threadIdx.x; i < NT * H; i += 256) sC[i] = g_teC[i];
    if (threadIdx.x < H) {
        sqb[threadIdx.x] = g_qbe[threadIdx.x];
        sW2[threadIdx.x] = Wes2[threadIdx.x];
    }
    __syncthreads();
    int g = threadIdx.x >> 4, sub = threadIdx.x & 15;
    int e = blockIdx.x * 16 + g;
    if (e >= N_EDGES) return;
    int s_ = src[e], d_ = dst[e], t_ = et[e];
    float4 a = ((const float4*)(g_A + (size_t)s_ * H))[sub];
    float4 b = ((const float4*)(g_B + (size_t)d_ * H))[sub];
    float4 c = ((const float4*)(sC + t_ * H))[sub];
    float4 q = ((const float4*)sqb)[sub];
    float h0 = fmaxf(a.x + b.x + c.x + q.x, 0.f);
    float h1 = fmaxf(a.y + b.y + c.y + q.y, 0.f);
    float h2 = fmaxf(a.z + b.z + c.z + q.z, 0.f);
    float h3 = fmaxf(a.w + b.w + c.w + q.w, 0.f);
    float4 w = ((const float4*)sW2)[sub];
    float part = h0 * w.x + h1 * w.y + h2 * w.z + h3 * w.w;
#pragma unroll
    for (int o = 8; o; o >>= 1) part += __shfl_down_sync(0xffffffffu, part, o, 16);
    if (sub == 0) {
        float lg = part + bes2[0];
        out_es[e] = 1.f / (1.f + expf(-lg));
    }
}

// ---------------- launch ----------------
extern "C" void kernel_launch(void* const* d_in, const int* in_sizes, int n_in,
                              void* d_out, int out_size) {
    const float* nf    = (const float*)d_in[0];
    const float* edesc = (const float*)d_in[1];
    const float* query = (const float*)d_in[2];
    const float* Wn    = (const float*)d_in[3];
    const float* bn    = (const float*)d_in[4];
    const float* ts    = (const float*)d_in[5];
    const float* Wq    = (const float*)d_in[6];
    const float* bq    = (const float*)d_in[7];
    const float* Ws    = (const float*)d_in[8];
    const float* bs    = (const float*)d_in[9];
    const float* attn  = (const float*)d_in[10];
    const float* Wmp   = (const float*)d_in[11];
    const float* bmp   = (const float*)d_in[12];
    const float* Wns1  = (const float*)d_in[13];
    const float* bns1  = (const float*)d_in[14];
    const float* Wns2  = (const float*)d_in[15];
    const float* bns2  = (const float*)d_in[16];
    const float* Wes1  = (const float*)d_in[17];
    const float* bes1  = (const float*)d_in[18];
    const float* Wes2  = (const float*)d_in[19];
    const float* bes2  = (const float*)d_in[20];
    const int* eidx    = (const int*)d_in[21];
    const int* etype   = (const int*)d_in[22];
    const int* src = eidx;
    const int* dst = eidx + N_EDGES;

    float* out_ns = (float*)d_out;
    float* out_es = out_ns + N_NODES;
    float* out_h  = out_es + N_EDGES;
    float* out_te = out_h + (size_t)N_NODES * H;

    const int NODE_BLOCKS = (N_NODES + 7) / 8;       // 6250
    const int EDGE_BLOCKS = (N_EDGES + 255) / 256;   // 3125
    const int EDGE_G16    = (N_EDGES + 15) / 16;     // 50000
    const int ZERO_BLOCKS = (N_NODES + 255) / 256;

    // constants + CSR build (CSR is reused by all 3 layers)
    k_consts<<<1, 256>>>(query, Wq, bq, edesc, Ws, bs, attn, Wns1, bns1, Wes1, bes1, out_te);
    k_zero<<<ZERO_BLOCKS, 256>>>();
    k_hist<<<EDGE_BLOCKS, 256>>>(dst);
    k_scan<<<1, 1024>>>();
    k_fill<<<EDGE_BLOCKS, 256>>>(src, dst, etype);

    // embed + layer-0 prep
    k_embed_prep<<<NODE_BLOCKS, 256>>>(nf, Wn, bn, ts, attn, Wmp, bmp, out_h);

    // layers
    k_layer_edge<<<NODE_BLOCKS, 256>>>(0);
    k_node_update<<<NODE_BLOCKS, 256>>>(attn + 1 * (2 * H + TD), Wmp + 1 * H * H, bmp + 1 * H, out_h);
    k_layer_edge<<<NODE_BLOCKS, 256>>>(1);
    k_node_update<<<NODE_BLOCKS, 256>>>(attn + 2 * (2 * H + TD), Wmp + 2 * H * H, bmp + 2 * H, out_h);
    k_layer_edge<<<NODE_BLOCKS, 256>>>(2);

    // readout
    k_final_node<<<NODE_BLOCKS, 256>>>(Wns1, Wns2, bns2, Wes1, out_h, out_ns);
    k_final_edge<<<EDGE_G16, 256>>>(src, dst, etype, Wes2, bes2, out_es);
}

// round 3
// speedup vs baseline: 1.7103x; 1.5944x over previous
#include <cuda_runtime.h>
#include <math.h>

#define N_NODES 50000
#define N_EDGES 800000
#define NLAYERS 3
#define NF 256
#define EF 64
#define QD 128
#define H  64
#define TD 32
#define NT 64
#define EPSF 1e-15f
#define ATANH_CLIP 6.1030245f   // atanh(1 - 1e-5)

// ---------------- scratch ----------------
__device__ __align__(16) float g_ht[N_NODES * H];
__device__ __align__(16) float g_msg[N_NODES * H];
__device__ __align__(16) float g_A[N_NODES * H];
__device__ __align__(16) float g_B[N_NODES * H];
__device__ float g_ps[N_NODES];
__device__ float g_pd[N_NODES];
__device__ float g_ex[N_EDGES];
__device__ float g_q[H];
__device__ float g_temb[NT * TD];
__device__ float g_pte[NLAYERS * NT];
__device__ __align__(16) float g_teC[NT * H];
__device__ float g_qbn[H];
__device__ float g_qbe[H];
// CSR
__device__ int g_cnt[N_NODES];
__device__ int g_fill[N_NODES];
__device__ int g_rowptr[N_NODES + 1];
__device__ int g_bsum[64];
__device__ int g_boff[64];
__device__ unsigned int g_pack[N_EDGES];

__device__ __forceinline__ float warpReduceSum(float v) {
#pragma unroll
    for (int o = 16; o; o >>= 1) v += __shfl_xor_sync(0xffffffffu, v, o);
    return v;
}
__device__ __forceinline__ float red8(float v) {
    v += __shfl_xor_sync(0xffffffffu, v, 1, 8);
    v += __shfl_xor_sync(0xffffffffu, v, 2, 8);
    v += __shfl_xor_sync(0xffffffffu, v, 4, 8);
    return v;
}

// ---------------- constants kernel ----------------
__global__ void k_consts(const float* __restrict__ query, const float* __restrict__ Wq,
                         const float* __restrict__ bq, const float* __restrict__ edesc,
                         const float* __restrict__ Ws, const float* __restrict__ bs,
                         const float* __restrict__ attn_a, const float* __restrict__ Wns1,
                         const float* __restrict__ bns1, const float* __restrict__ Wes1,
                         const float* __restrict__ bes1, float* __restrict__ out_te) {
    int t = threadIdx.x;
    if (t < H) {
        float a = bq[t];
        for (int k = 0; k < QD; k++) a += query[k] * Wq[k * H + t];
        g_q[t] = a;
    }
    __syncthreads();
    for (int i = t; i < NT * TD; i += 256) {
        int ty = i / TD, j = i % TD;
        float a = bs[j];
        for (int k = 0; k < EF; k++) a += edesc[ty * EF + k] * Ws[k * TD + j];
        a = tanhf(a);
        g_temb[i] = a;
        out_te[i] = a;
    }
    __syncthreads();
    for (int i = t; i < NLAYERS * NT; i += 256) {
        int l = i / NT, ty = i % NT;
        float a = 0.f;
        for (int j = 0; j < TD; j++) a += g_temb[ty * TD + j] * attn_a[l * (2 * H + TD) + 2 * H + j];
        g_pte[i] = a;
    }
    for (int i = t; i < NT * H; i += 256) {
        int ty = i / H, j = i % H;
        float a = 0.f;
        for (int k = 0; k < TD; k++) a += g_temb[ty * TD + k] * Wes1[(2 * H + k) * H + j];
        g_teC[i] = a;
    }
    if (t < H) {
        float a = bns1[t];
        for (int k = 0; k < H; k++) a += g_q[k] * Wns1[(H + k) * H + t];
        g_qbn[t] = a;
        float b = bes1[t];
        for (int k = 0; k < H; k++) b += g_q[k] * Wes1[(2 * H + TD + k) * H + t];
        g_qbe[t] = b;
    }
}

// ---------------- CSR build ----------------
__global__ void k_zero() {
    int i = blockIdx.x * 256 + threadIdx.x;
    if (i < N_NODES) { g_cnt[i] = 0; g_fill[i] = 0; }
}
__global__ void k_hist(const int* __restrict__ dst) {
    int e = blockIdx.x * 256 + threadIdx.x;
    if (e < N_EDGES) atomicAdd(&g_cnt[dst[e]], 1);
}
__global__ void k_scan_part() {
    __shared__ int ws[32];
    int b = blockIdx.x, t = threadIdx.x;
    int idx = b * 1024 + t;
    int v = (idx < N_NODES) ? g_cnt[idx] : 0;
    int lane = t & 31, wid = t >> 5;
    int x = v;
#pragma unroll
    for (int o = 1; o < 32; o <<= 1) {
        int tv = __shfl_up_sync(0xffffffffu, x, o);
        if (lane >= o) x += tv;
    }
    if (lane == 31) ws[wid] = x;
    __syncthreads();
    if (wid == 0) {
        int w = ws[lane];
#pragma unroll
        for (int o = 1; o < 32; o <<= 1) {
            int tv = __shfl_up_sync(0xffffffffu, w, o);
            if (lane >= o) w += tv;
        }
        ws[lane] = w;
    }
    __syncthreads();
    int incl = x + (wid > 0 ? ws[wid - 1] : 0);
    if (idx < N_NODES) g_rowptr[idx + 1] = incl;
    if (t == 1023) g_bsum[b] = incl;
}
__global__ void k_scan_top(int nblk) {
    __shared__ int s[64];
    int t = threadIdx.x;
    s[t] = (t < nblk) ? g_bsum[t] : 0;
    __syncthreads();
    if (t == 0) {
        int acc = 0;
        for (int i = 0; i < 64; i++) { int tmp = s[i]; s[i] = acc; acc += tmp; }
    }
    __syncthreads();
    g_boff[t] = s[t];
}
__global__ void k_scan_add() {
    int b = blockIdx.x, t = threadIdx.x;
    int idx = b * 1024 + t;
    if (idx < N_NODES) g_rowptr[idx + 1] += g_boff[b];
    if (b == 0 && t == 0) g_rowptr[0] = 0;
}
__global__ void k_fill(const int* __restrict__ src, const int* __restrict__ dst,
                       const int* __restrict__ et) {
    int e = blockIdx.x * 256 + threadIdx.x;
    if (e >= N_EDGES) return;
    int d = dst[e];
    int pos = g_rowptr[d] + atomicAdd(&g_fill[d], 1);
    g_pack[pos] = (unsigned int)src[e] | ((unsigned int)et[e] << 16);
}

// ---------------- register-tiled GEMM helpers (64x64 tile, 128 threads, 4x8/thread) ----------------
__device__ __forceinline__ void load_A64(const float* __restrict__ A, int lda, int row0,
                                         int kbase, float* __restrict__ sA) {
    int tid = threadIdx.x;
#pragma unroll
    for (int it = 0; it < 8; it++) {
        int r = (tid >> 4) + it * 8;
        int k4 = (tid & 15) * 4;
        int grow = row0 + r;
        float4 v = make_float4(0.f, 0.f, 0.f, 0.f);
        if (grow < N_NODES) v = *(const float4*)(A + (size_t)grow * lda + kbase + k4);
        *(float4*)(sA + r * 68 + k4) = v;
    }
}
__device__ __forceinline__ void load_B64(const float* __restrict__ W, float* __restrict__ sB) {
    int tid = threadIdx.x;
#pragma unroll
    for (int it = 0; it < 8; it++) {
        int k = (tid >> 4) + it * 8;
        int c4 = (tid & 15) * 4;
        *(float4*)(sB + k * 64 + c4) = *(const float4*)(W + (size_t)k * 64 + c4);
    }
}
__device__ __forceinline__ void gemm_frag(const float* __restrict__ sA, const float* __restrict__ sB,
                                          int r0, int c0, float c[4][8]) {
#pragma unroll 8
    for (int k = 0; k < 64; k++) {
        float4 b0 = *(const float4*)(sB + k * 64 + c0);
        float4 b1 = *(const float4*)(sB + k * 64 + c0 + 4);
        float av[4];
        av[0] = sA[(r0 + 0) * 68 + k];
        av[1] = sA[(r0 + 1) * 68 + k];
        av[2] = sA[(r0 + 2) * 68 + k];
        av[3] = sA[(r0 + 3) * 68 + k];
        float bv[8] = {b0.x, b0.y, b0.z, b0.w, b1.x, b1.y, b1.z, b1.w};
#pragma unroll
        for (int i = 0; i < 4; i++)
#pragma unroll
            for (int j = 0; j < 8; j++) c[i][j] = fmaf(av[i], bv[j], c[i][j]);
    }
}

// ---------------- embed: ht0 = clip((nf@Wn + bn)*ts) ----------------
__global__ void __launch_bounds__(128) k_embed(const float* __restrict__ nf,
                                               const float* __restrict__ Wn,
                                               const float* __restrict__ bn,
                                               const float* __restrict__ ts_p) {
    __shared__ __align__(16) float sA[64 * 68];
    __shared__ __align__(16) float sB[64 * 64];
    __shared__ float sbn[64];
    int tid = threadIdx.x;
    int row0 = blockIdx.x * 64;
    if (tid < 64) sbn[tid] = bn[tid];
    float c[4][8];
#pragma unroll
    for (int i = 0; i < 4; i++)
#pragma unroll
        for (int j = 0; j < 8; j++) c[i][j] = 0.f;
    int rt = tid >> 3, ct = tid & 7;
    int r0 = rt * 4, c0 = ct * 8;
    for (int ch = 0; ch < 4; ch++) {
        __syncthreads();
        load_A64(nf, NF, row0, ch * 64, sA);
        load_B64(Wn + (size_t)ch * 64 * 64, sB);
        __syncthreads();
        gemm_frag(sA, sB, r0, c0, c);
    }
    float ts = ts_p[0];
    float u[4][8];
#pragma unroll
    for (int i = 0; i < 4; i++) {
        float nn = 0.f;
#pragma unroll
        for (int j = 0; j < 8; j++) {
            u[i][j] = (c[i][j] + sbn[c0 + j]) * ts;
            nn += u[i][j] * u[i][j];
        }
        nn = red8(nn);
        float n = fmaxf(sqrtf(nn), EPSF);
        float th = tanhf(n);
        float fac = (th < 1.f - 1e-5f) ? 1.f : ATANH_CLIP / n;
        int grow = row0 + r0 + i;
        if (grow < N_NODES) {
            float4 o0 = make_float4(u[i][0] * fac, u[i][1] * fac, u[i][2] * fac, u[i][3] * fac);
            float4 o1 = make_float4(u[i][4] * fac, u[i][5] * fac, u[i][6] * fac, u[i][7] * fac);
            *(float4*)(g_ht + (size_t)grow * H + c0) = o0;
            *(float4*)(g_ht + (size_t)grow * H + c0 + 4) = o1;
        }
    }
}

// ---------------- msg GEMM + ps/pd ----------------
__global__ void __launch_bounds__(128) k_msg(const float* __restrict__ WmpL,
                                             const float* __restrict__ bmpL,
                                             const float* __restrict__ attnL) {
    __shared__ __align__(16) float sA[64 * 68];
    __shared__ __align__(16) float sB[64 * 64];
    __shared__ float sb[64], sa1[64], sa2[64];
    int tid = threadIdx.x;
    int row0 = blockIdx.x * 64;
    if (tid < 64) {
        sb[tid] = bmpL[tid];
        sa1[tid] = attnL[tid];
        sa2[tid] = attnL[H + tid];
    }
    load_A64(g_ht, H, row0, 0, sA);
    load_B64(WmpL, sB);
    __syncthreads();
    int rt = tid >> 3, ct = tid & 7;
    int r0 = rt * 4, c0 = ct * 8;
    float c[4][8];
#pragma unroll
    for (int i = 0; i < 4; i++)
#pragma unroll
        for (int j = 0; j < 8; j++) c[i][j] = 0.f;
    float ps[4] = {0.f, 0.f, 0.f, 0.f}, pd[4] = {0.f, 0.f, 0.f, 0.f};
#pragma unroll 8
    for (int k = 0; k < 64; k++) {
        float4 b0 = *(const float4*)(sB + k * 64 + c0);
        float4 b1 = *(const float4*)(sB + k * 64 + c0 + 4);
        float a1k = sa1[k], a2k = sa2[k];
        float av[4];
        av[0] = sA[(r0 + 0) * 68 + k];
        av[1] = sA[(r0 + 1) * 68 + k];
        av[2] = sA[(r0 + 2) * 68 + k];
        av[3] = sA[(r0 + 3) * 68 + k];
        float bv[8] = {b0.x, b0.y, b0.z, b0.w, b1.x, b1.y, b1.z, b1.w};
#pragma unroll
        for (int i = 0; i < 4; i++) {
#pragma unroll
            for (int j = 0; j < 8; j++) c[i][j] = fmaf(av[i], bv[j], c[i][j]);
            ps[i] = fmaf(av[i], a1k, ps[i]);
            pd[i] = fmaf(av[i], a2k, pd[i]);
        }
    }
#pragma unroll
    for (int i = 0; i < 4; i++) {
        int grow = row0 + r0 + i;
        if (grow < N_NODES) {
            float4 o0 = make_float4(c[i][0] + sb[c0], c[i][1] + sb[c0 + 1],
                                    c[i][2] + sb[c0 + 2], c[i][3] + sb[c0 + 3]);
            float4 o1 = make_float4(c[i][4] + sb[c0 + 4], c[i][5] + sb[c0 + 5],
                                    c[i][6] + sb[c0 + 6], c[i][7] + sb[c0 + 7]);
            *(float4*)(g_msg + (size_t)grow * H + c0) = o0;
            *(float4*)(g_msg + (size_t)grow * H + c0 + 4) = o1;
            if (ct == 0) { g_ps[grow] = ps[i]; g_pd[grow] = pd[i]; }
        }
    }
}

// ---------------- layer edge: softmax + aggregate + clip(relu) ----------------
__global__ void k_layer_edge(int l, int last, float* __restrict__ out_h) {
    __shared__ float spte[NT];
    if (threadIdx.x < NT) spte[threadIdx.x] = g_pte[l * NT + threadIdx.x];
    __syncthreads();
    int warp = threadIdx.x >> 5, lane = threadIdx.x & 31;
    int d = blockIdx.x * 8 + warp;
    if (d >= N_NODES) return;
    int row0 = g_rowptr[d];
    int deg = g_rowptr[d + 1] - row0;
    float acc0 = 0.f, acc1 = 0.f;
    if (deg > 0) {
        float pdv = g_pd[d];
        float s0 = 0.f, s1 = 0.f, s2 = 0.f, s3 = 0.f;
        float smax = -1e30f;
        for (int i = lane, c = 0; i < deg; i += 32, c++) {
            unsigned int p = g_pack[row0 + i];
            float s = g_ps[p & 0xffffu] + pdv + spte[p >> 16];
            s = s > 0.f ? s : 0.2f * s;
            if (c == 0) s0 = s; else if (c == 1) s1 = s;
            else if (c == 2) s2 = s; else if (c == 3) s3 = s;
            else g_ex[row0 + i] = s;
            smax = fmaxf(smax, s);
        }
#pragma unroll
        for (int o = 16; o; o >>= 1) smax = fmaxf(smax, __shfl_xor_sync(0xffffffffu, smax, o));
        float den = 0.f;
        for (int i = lane, c = 0; i < deg; i += 32, c++) {
            float s = (c == 0) ? s0 : (c == 1) ? s1 : (c == 2) ? s2 : (c == 3) ? s3 : g_ex[row0 + i];
            float ex = expf(s - smax);
            if (c == 0) s0 = ex; else if (c == 1) s1 = ex;
            else if (c == 2) s2 = ex; else if (c == 3) s3 = ex;
            else g_ex[row0 + i] = ex;
            den += ex;
        }
        den = warpReduceSum(den);
        float inv = 1.f / (den + EPSF);
#pragma unroll 2
        for (int j = 0; j < deg; j++) {
            int owner = j & 31, c = j >> 5;
            float ex;
            if (c < 4) {
                float v = (c == 0) ? s0 : (c == 1) ? s1 : (c == 2) ? s2 : s3;
                ex = __shfl_sync(0xffffffffu, v, owner);
            } else {
                ex = g_ex[row0 + j];
            }
            unsigned int p = g_pack[row0 + j];
            int sn = p & 0xffffu;
            float w = ex * inv;
            acc0 += w * g_msg[sn * H + lane];
            acc1 += w * g_msg[sn * H + lane + 32];
        }
    }
    float u0 = fmaxf(acc0, 0.f), u1 = fmaxf(acc1, 0.f);
    float nn = warpReduceSum(u0 * u0 + u1 * u1);
    float n = fmaxf(sqrtf(nn), EPSF);
    float th = tanhf(n);
    float fac = (th < 1.f - 1e-5f) ? 1.f : ATANH_CLIP / n;
    g_ht[d * H + lane] = u0 * fac;
    g_ht[d * H + lane + 32] = u1 * fac;
    if (last) {
        float fh = th / n;
        out_h[d * H + lane] = u0 * fh;
        out_h[d * H + lane + 32] = u1 * fh;
    }
}

// ---------------- final node: 3 GEMMs from ht_final ----------------
__global__ void __launch_bounds__(128) k_final_node(const float* __restrict__ Wns1,
                                                    const float* __restrict__ Wns2,
                                                    const float* __restrict__ bns2,
                                                    const float* __restrict__ Wes1,
                                                    float* __restrict__ out_ns) {
    __shared__ __align__(16) float sA[64 * 68];
    __shared__ __align__(16) float sB[64 * 64];
    __shared__ float sqb[64], sw2[64];
    int tid = threadIdx.x;
    int row0 = blockIdx.x * 64;
    if (tid < 64) {
        sqb[tid] = g_qbn[tid];
        sw2[tid] = Wns2[tid];
    }
    load_A64(g_ht, H, row0, 0, sA);
    int rt = tid >> 3, ct = tid & 7;
    int r0 = rt * 4, c0 = ct * 8;
    const float* Wp[3] = {Wns1, Wes1, Wes1 + 64 * 64};
#pragma unroll
    for (int ph = 0; ph < 3; ph++) {
        __syncthreads();
        load_B64(Wp[ph], sB);
        __syncthreads();
        float c[4][8];
#pragma unroll
        for (int i = 0; i < 4; i++)
#pragma unroll
            for (int j = 0; j < 8; j++) c[i][j] = 0.f;
        gemm_frag(sA, sB, r0, c0, c);
        if (ph == 0) {
#pragma unroll
            for (int i = 0; i < 4; i++) {
                float dot = 0.f;
#pragma unroll
                for (int j = 0; j < 8; j++) {
                    float hn = fmaxf(c[i][j] + sqb[c0 + j], 0.f);
                    dot = fmaf(hn, sw2[c0 + j], dot);
                }
                dot = red8(dot);
                int grow = row0 + r0 + i;
                if (ct == 0 && grow < N_NODES) {
                    float lg = dot + bns2[0];
                    out_ns[grow] = 1.f / (1.f + expf(-lg));
                }
            }
        } else {
            float* dstp = (ph == 1) ? g_A : g_B;
#pragma unroll
            for (int i = 0; i < 4; i++) {
                int grow = row0 + r0 + i;
                if (grow < N_NODES) {
                    float4 o0 = make_float4(c[i][0], c[i][1], c[i][2], c[i][3]);
                    float4 o1 = make_float4(c[i][4], c[i][5], c[i][6], c[i][7]);
                    *(float4*)(dstp + (size_t)grow * H + c0) = o0;
                    *(float4*)(dstp + (size_t)grow * H + c0 + 4) = o1;
                }
            }
        }
    }
}

// ---------------- final edge scores ----------------
__global__ void k_final_edge(const int* __restrict__ src, const int* __restrict__ dst,
                             const int* __restrict__ et, const float* __restrict__ Wes2,
                             const float* __restrict__ bes2, float* __restrict__ out_es) {
    __shared__ __align__(16) float sC[NT * H];
    __shared__ __align__(16) float sqb[H];
    __shared__ __align__(16) float sW2[H];
    for (int i = threadIdx.x; i < NT * H; i += 256) sC[i] = g_teC[i];
    if (threadIdx.x < H) {
        sqb[threadIdx.x] = g_qbe[threadIdx.x];
        sW2[threadIdx.x] = Wes2[threadIdx.x];
    }
    __syncthreads();
    int g = threadIdx.x >> 4, sub = threadIdx.x & 15;
    int e = blockIdx.x * 16 + g;
    if (e >= N_EDGES) return;
    int s_ = src[e], d_ = dst[e], t_ = et[e];
    float4 a = ((const float4*)(g_A + (size_t)s_ * H))[sub];
    float4 b = ((const float4*)(g_B + (size_t)d_ * H))[sub];
    float4 c = ((const float4*)(sC + t_ * H))[sub];
    float4 q = ((const float4*)sqb)[sub];
    float h0 = fmaxf(a.x + b.x + c.x + q.x, 0.f);
    float h1 = fmaxf(a.y + b.y + c.y + q.y, 0.f);
    float h2 = fmaxf(a.z + b.z + c.z + q.z, 0.f);
    float h3 = fmaxf(a.w + b.w + c.w + q.w, 0.f);
    float4 w = ((const float4*)sW2)[sub];
    float part = h0 * w.x + h1 * w.y + h2 * w.z + h3 * w.w;
#pragma unroll
    for (int o = 8; o; o >>= 1) part += __shfl_down_sync(0xffffffffu, part, o, 16);
    if (sub == 0) {
        float lg = part + bes2[0];
        out_es[e] = 1.f / (1.f + expf(-lg));
    }
}

// ---------------- launch ----------------
extern "C" void kernel_launch(void* const* d_in, const int* in_sizes, int n_in,
                              void* d_out, int out_size) {
    const float* nf    = (const float*)d_in[0];
    const float* edesc = (const float*)d_in[1];
    const float* query = (const float*)d_in[2];
    const float* Wn    = (const float*)d_in[3];
    const float* bn    = (const float*)d_in[4];
    const float* ts    = (const float*)d_in[5];
    const float* Wq    = (const float*)d_in[6];
    const float* bq    = (const float*)d_in[7];
    const float* Ws    = (const float*)d_in[8];
    const float* bs    = (const float*)d_in[9];
    const float* attn  = (const float*)d_in[10];
    const float* Wmp   = (const float*)d_in[11];
    const float* bmp   = (const float*)d_in[12];
    const float* Wns1  = (const float*)d_in[13];
    const float* bns1  = (const float*)d_in[14];
    const float* Wns2  = (const float*)d_in[15];
    const float* bns2  = (const float*)d_in[16];
    const float* Wes1  = (const float*)d_in[17];
    const float* bes1  = (const float*)d_in[18];
    const float* Wes2  = (const float*)d_in[19];
    const float* bes2  = (const float*)d_in[20];
    const int* eidx    = (const int*)d_in[21];
    const int* etype   = (const int*)d_in[22];
    const int* src = eidx;
    const int* dst = eidx + N_EDGES;

    float* out_ns = (float*)d_out;
    float* out_es = out_ns + N_NODES;
    float* out_h  = out_es + N_EDGES;
    float* out_te = out_h + (size_t)N_NODES * H;

    const int NB64        = (N_NODES + 63) / 64;      // 782
    const int NODE_BLOCKS = (N_NODES + 7) / 8;        // 6250
    const int EDGE_BLOCKS = (N_EDGES + 255) / 256;    // 3125
    const int EDGE_G16    = (N_EDGES + 15) / 16;      // 50000
    const int ZERO_BLOCKS = (N_NODES + 255) / 256;
    const int SCAN_BLOCKS = (N_NODES + 1023) / 1024;  // 49

    k_consts<<<1, 256>>>(query, Wq, bq, edesc, Ws, bs, attn, Wns1, bns1, Wes1, bes1, out_te);
    k_zero<<<ZERO_BLOCKS, 256>>>();
    k_hist<<<EDGE_BLOCKS, 256>>>(dst);
    k_scan_part<<<SCAN_BLOCKS, 1024>>>();
    k_scan_top<<<1, 64>>>(SCAN_BLOCKS);
    k_scan_add<<<SCAN_BLOCKS, 1024>>>();
    k_fill<<<EDGE_BLOCKS, 256>>>(src, dst, etype);

    k_embed<<<NB64, 128>>>(nf, Wn, bn, ts);

    for (int l = 0; l < NLAYERS; l++) {
        k_msg<<<NB64, 128>>>(Wmp + (size_t)l * H * H, bmp + l * H, attn + l * (2 * H + TD));
        k_layer_edge<<<NODE_BLOCKS, 256>>>(l, (l == NLAYERS - 1) ? 1 : 0, out_h);
    }

    k_final_node<<<NB64, 128>>>(Wns1, Wns2, bns2, Wes1, out_ns);
    k_final_edge<<<EDGE_G16, 256>>>(src, dst, etype, Wes2, bes2, out_es);
}

// round 4
// speedup vs baseline: 2.0079x; 1.1740x over previous
#include <cuda_runtime.h>
#include <math.h>

#define N_NODES 50000
#define N_EDGES 800000
#define NLAYERS 3
#define NF 256
#define EF 64
#define QD 128
#define H  64
#define TD 32
#define NT 64
#define EPSF 1e-15f
#define ATANH_CLIP 6.1030245f   // atanh(1 - 1e-5)

// ---------------- scratch ----------------
__device__ __align__(16) float g_ht[N_NODES * H];
__device__ __align__(16) float g_msg[N_NODES * H];
__device__ __align__(16) float g_A[N_NODES * H];
__device__ __align__(16) float g_B[N_NODES * H];
__device__ float g_ps[N_NODES];
__device__ float g_pd[N_NODES];
__device__ float g_ex[N_EDGES];
__device__ float g_q[H];
__device__ float g_temb[NT * TD];
__device__ float g_pte[NLAYERS * NT];
__device__ __align__(16) float g_teC[NT * H];   // temb@Wes1[2H:2H+TD] + qbe (folded)
__device__ float g_qbn[H];
__device__ float g_qbe[H];
// CSR
__device__ int g_cnt[N_NODES];
__device__ int g_fill[N_NODES];
__device__ int g_rowptr[N_NODES + 1];
__device__ int g_bsum[64];
__device__ int g_boff[64];
__device__ unsigned int g_pack[N_EDGES];  // src(16) | type<<16
__device__ int g_eord[N_EDGES];           // original edge index

__device__ __forceinline__ float warpReduceSum(float v) {
#pragma unroll
    for (int o = 16; o; o >>= 1) v += __shfl_xor_sync(0xffffffffu, v, o);
    return v;
}
__device__ __forceinline__ float red8(float v) {
    v += __shfl_xor_sync(0xffffffffu, v, 1, 8);
    v += __shfl_xor_sync(0xffffffffu, v, 2, 8);
    v += __shfl_xor_sync(0xffffffffu, v, 4, 8);
    return v;
}
#define FMA2(d, a, b) asm("fma.rn.f32x2 %0, %1, %2, %3;" : "=l"(d) : "l"(a), "l"(b), "l"(d))
__device__ __forceinline__ float2 up2(unsigned long long v) {
    float2 r;
    asm("mov.b64 {%0, %1}, %2;" : "=f"(r.x), "=f"(r.y) : "l"(v));
    return r;
}

// ---------------- constants kernel ----------------
__global__ void k_consts(const float* __restrict__ query, const float* __restrict__ Wq,
                         const float* __restrict__ bq, const float* __restrict__ edesc,
                         const float* __restrict__ Ws, const float* __restrict__ bs,
                         const float* __restrict__ attn_a, const float* __restrict__ Wns1,
                         const float* __restrict__ bns1, const float* __restrict__ Wes1,
                         const float* __restrict__ bes1, float* __restrict__ out_te) {
    int t = threadIdx.x;
    if (t < H) {
        float a = bq[t];
        for (int k = 0; k < QD; k++) a += query[k] * Wq[k * H + t];
        g_q[t] = a;
    }
    __syncthreads();
    for (int i = t; i < NT * TD; i += 256) {
        int ty = i / TD, j = i % TD;
        float a = bs[j];
        for (int k = 0; k < EF; k++) a += edesc[ty * EF + k] * Ws[k * TD + j];
        a = tanhf(a);
        g_temb[i] = a;
        out_te[i] = a;
    }
    if (t < H) {
        float a = bns1[t];
        for (int k = 0; k < H; k++) a += g_q[k] * Wns1[(H + k) * H + t];
        g_qbn[t] = a;
        float b = bes1[t];
        for (int k = 0; k < H; k++) b += g_q[k] * Wes1[(2 * H + TD + k) * H + t];
        g_qbe[t] = b;
    }
    __syncthreads();
    for (int i = t; i < NLAYERS * NT; i += 256) {
        int l = i / NT, ty = i % NT;
        float a = 0.f;
        for (int j = 0; j < TD; j++) a += g_temb[ty * TD + j] * attn_a[l * (2 * H + TD) + 2 * H + j];
        g_pte[i] = a;
    }
    for (int i = t; i < NT * H; i += 256) {
        int ty = i / H, j = i % H;
        float a = g_qbe[j];
        for (int k = 0; k < TD; k++) a += g_temb[ty * TD + k] * Wes1[(2 * H + k) * H + j];
        g_teC[i] = a;
    }
}

// ---------------- CSR build ----------------
__global__ void k_zero() {
    int i = blockIdx.x * 256 + threadIdx.x;
    if (i < N_NODES) { g_cnt[i] = 0; g_fill[i] = 0; }
}
__global__ void k_hist(const int* __restrict__ dst) {
    int e = blockIdx.x * 256 + threadIdx.x;
    if (e < N_EDGES) atomicAdd(&g_cnt[dst[e]], 1);
}
__global__ void k_scan_part() {
    __shared__ int ws[32];
    int b = blockIdx.x, t = threadIdx.x;
    int idx = b * 1024 + t;
    int v = (idx < N_NODES) ? g_cnt[idx] : 0;
    int lane = t & 31, wid = t >> 5;
    int x = v;
#pragma unroll
    for (int o = 1; o < 32; o <<= 1) {
        int tv = __shfl_up_sync(0xffffffffu, x, o);
        if (lane >= o) x += tv;
    }
    if (lane == 31) ws[wid] = x;
    __syncthreads();
    if (wid == 0) {
        int w = ws[lane];
#pragma unroll
        for (int o = 1; o < 32; o <<= 1) {
            int tv = __shfl_up_sync(0xffffffffu, w, o);
            if (lane >= o) w += tv;
        }
        ws[lane] = w;
    }
    __syncthreads();
    int incl = x + (wid > 0 ? ws[wid - 1] : 0);
    if (idx < N_NODES) g_rowptr[idx + 1] = incl;
    if (t == 1023) g_bsum[b] = incl;
}
__global__ void k_scan_top(int nblk) {
    __shared__ int s[64];
    int t = threadIdx.x;
    s[t] = (t < nblk) ? g_bsum[t] : 0;
    __syncthreads();
    if (t == 0) {
        int acc = 0;
        for (int i = 0; i < 64; i++) { int tmp = s[i]; s[i] = acc; acc += tmp; }
    }
    __syncthreads();
    g_boff[t] = s[t];
}
__global__ void k_scan_add() {
    int b = blockIdx.x, t = threadIdx.x;
    int idx = b * 1024 + t;
    if (idx < N_NODES) g_rowptr[idx + 1] += g_boff[b];
    if (b == 0 && t == 0) g_rowptr[0] = 0;
}
__global__ void k_fill(const int* __restrict__ src, const int* __restrict__ dst,
                       const int* __restrict__ et) {
    int e = blockIdx.x * 256 + threadIdx.x;
    if (e >= N_EDGES) return;
    int d = dst[e];
    int pos = g_rowptr[d] + atomicAdd(&g_fill[d], 1);
    g_pack[pos] = (unsigned int)src[e] | ((unsigned int)et[e] << 16);
    g_eord[pos] = e;
}

// ---------------- f32x2 register-tiled GEMM (64x64 tile, 128 thr, 4x8/thr) ----------------
// sA2: A staged as duplicated float2 {a,a}, row stride 66 (float2 units)
__device__ __forceinline__ void load_A64_dup(const float* __restrict__ A, int lda, int row0,
                                             int kbase, float2* __restrict__ sA2) {
    int tid = threadIdx.x;
#pragma unroll
    for (int it = 0; it < 8; it++) {
        int r = (tid >> 4) + it * 8;
        int k4 = (tid & 15) * 4;
        int grow = row0 + r;
        float4 v = make_float4(0.f, 0.f, 0.f, 0.f);
        if (grow < N_NODES) v = *(const float4*)(A + (size_t)grow * lda + kbase + k4);
        float2* p = sA2 + r * 66 + k4;
        p[0] = make_float2(v.x, v.x);
        p[1] = make_float2(v.y, v.y);
        p[2] = make_float2(v.z, v.z);
        p[3] = make_float2(v.w, v.w);
    }
}
__device__ __forceinline__ void load_B64(const float* __restrict__ W, float* __restrict__ sB) {
    int tid = threadIdx.x;
#pragma unroll
    for (int it = 0; it < 8; it++) {
        int k = (tid >> 4) + it * 8;
        int c4 = (tid & 15) * 4;
        *(float4*)(sB + k * 64 + c4) = *(const float4*)(W + (size_t)k * 64 + c4);
    }
}
__device__ __forceinline__ void gemm_frag2(const float2* __restrict__ sA2,
                                           const float* __restrict__ sB,
                                           int r0, int c0, unsigned long long c2[4][4]) {
#pragma unroll 4
    for (int k = 0; k < 64; k++) {
        ulonglong2 b01 = *(const ulonglong2*)(sB + k * 64 + c0);
        ulonglong2 b23 = *(const ulonglong2*)(sB + k * 64 + c0 + 4);
        unsigned long long aa0 = *(const unsigned long long*)(sA2 + (r0 + 0) * 66 + k);
        unsigned long long aa1 = *(const unsigned long long*)(sA2 + (r0 + 1) * 66 + k);
        unsigned long long aa2 = *(const unsigned long long*)(sA2 + (r0 + 2) * 66 + k);
        unsigned long long aa3 = *(const unsigned long long*)(sA2 + (r0 + 3) * 66 + k);
        FMA2(c2[0][0], aa0, b01.x); FMA2(c2[0][1], aa0, b01.y);
        FMA2(c2[0][2], aa0, b23.x); FMA2(c2[0][3], aa0, b23.y);
        FMA2(c2[1][0], aa1, b01.x); FMA2(c2[1][1], aa1, b01.y);
        FMA2(c2[1][2], aa1, b23.x); FMA2(c2[1][3], aa1, b23.y);
        FMA2(c2[2][0], aa2, b01.x); FMA2(c2[2][1], aa2, b01.y);
        FMA2(c2[2][2], aa2, b23.x); FMA2(c2[2][3], aa2, b23.y);
        FMA2(c2[3][0], aa3, b01.x); FMA2(c2[3][1], aa3, b01.y);
        FMA2(c2[3][2], aa3, b23.x); FMA2(c2[3][3], aa3, b23.y);
    }
}
#define ZERO_C2(c2) do { \
    _Pragma("unroll") for (int i = 0; i < 4; i++) \
    _Pragma("unroll") for (int j = 0; j < 4; j++) c2[i][j] = 0ull; } while (0)

// ---------------- embed: ht0 = clip((nf@Wn + bn)*ts) ----------------
__global__ void __launch_bounds__(128) k_embed(const float* __restrict__ nf,
                                               const float* __restrict__ Wn,
                                               const float* __restrict__ bn,
                                               const float* __restrict__ ts_p) {
    __shared__ __align__(16) float2 sA2[64 * 66];
    __shared__ __align__(16) float sB[64 * 64];
    __shared__ float sbn[64];
    int tid = threadIdx.x;
    int row0 = blockIdx.x * 64;
    if (tid < 64) sbn[tid] = bn[tid];
    unsigned long long c2[4][4];
    ZERO_C2(c2);
    int rt = tid >> 3, ct = tid & 7;
    int r0 = rt * 4, c0 = ct * 8;
    for (int ch = 0; ch < 4; ch++) {
        __syncthreads();
        load_A64_dup(nf, NF, row0, ch * 64, sA2);
        load_B64(Wn + (size_t)ch * 64 * 64, sB);
        __syncthreads();
        gemm_frag2(sA2, sB, r0, c0, c2);
    }
    float ts = ts_p[0];
#pragma unroll
    for (int i = 0; i < 4; i++) {
        float2 p0 = up2(c2[i][0]), p1 = up2(c2[i][1]), p2 = up2(c2[i][2]), p3 = up2(c2[i][3]);
        float u[8] = {p0.x, p0.y, p1.x, p1.y, p2.x, p2.y, p3.x, p3.y};
        float nn = 0.f;
#pragma unroll
        for (int j = 0; j < 8; j++) {
            u[j] = (u[j] + sbn[c0 + j]) * ts;
            nn += u[j] * u[j];
        }
        nn = red8(nn);
        float n = fmaxf(sqrtf(nn), EPSF);
        float th = tanhf(n);
        float fac = (th < 1.f - 1e-5f) ? 1.f : ATANH_CLIP / n;
        int grow = row0 + r0 + i;
        if (grow < N_NODES) {
            float4 o0 = make_float4(u[0] * fac, u[1] * fac, u[2] * fac, u[3] * fac);
            float4 o1 = make_float4(u[4] * fac, u[5] * fac, u[6] * fac, u[7] * fac);
            *(float4*)(g_ht + (size_t)grow * H + c0) = o0;
            *(float4*)(g_ht + (size_t)grow * H + c0 + 4) = o1;
        }
    }
}

// ---------------- msg GEMM + ps/pd ----------------
__global__ void __launch_bounds__(128) k_msg(const float* __restrict__ WmpL,
                                             const float* __restrict__ bmpL,
                                             const float* __restrict__ attnL) {
    __shared__ __align__(16) float2 sA2[64 * 66];
    __shared__ __align__(16) float sB[64 * 64];
    __shared__ float sb[64];
    __shared__ __align__(8) float2 sa12[64];
    int tid = threadIdx.x;
    int row0 = blockIdx.x * 64;
    if (tid < 64) {
        sb[tid] = bmpL[tid];
        sa12[tid] = make_float2(attnL[tid], attnL[H + tid]);
    }
    load_A64_dup(g_ht, H, row0, 0, sA2);
    load_B64(WmpL, sB);
    __syncthreads();
    int rt = tid >> 3, ct = tid & 7;
    int r0 = rt * 4, c0 = ct * 8;
    unsigned long long c2[4][4];
    ZERO_C2(c2);
    unsigned long long psd[4] = {0ull, 0ull, 0ull, 0ull};
#pragma unroll 4
    for (int k = 0; k < 64; k++) {
        ulonglong2 b01 = *(const ulonglong2*)(sB + k * 64 + c0);
        ulonglong2 b23 = *(const ulonglong2*)(sB + k * 64 + c0 + 4);
        unsigned long long a12 = *(const unsigned long long*)(sa12 + k);
        unsigned long long aa0 = *(const unsigned long long*)(sA2 + (r0 + 0) * 66 + k);
        unsigned long long aa1 = *(const unsigned long long*)(sA2 + (r0 + 1) * 66 + k);
        unsigned long long aa2 = *(const unsigned long long*)(sA2 + (r0 + 2) * 66 + k);
        unsigned long long aa3 = *(const unsigned long long*)(sA2 + (r0 + 3) * 66 + k);
        FMA2(c2[0][0], aa0, b01.x); FMA2(c2[0][1], aa0, b01.y);
        FMA2(c2[0][2], aa0, b23.x); FMA2(c2[0][3], aa0, b23.y);
        FMA2(psd[0], aa0, a12);
        FMA2(c2[1][0], aa1, b01.x); FMA2(c2[1][1], aa1, b01.y);
        FMA2(c2[1][2], aa1, b23.x); FMA2(c2[1][3], aa1, b23.y);
        FMA2(psd[1], aa1, a12);
        FMA2(c2[2][0], aa2, b01.x); FMA2(c2[2][1], aa2, b01.y);
        FMA2(c2[2][2], aa2, b23.x); FMA2(c2[2][3], aa2, b23.y);
        FMA2(psd[2], aa2, a12);
        FMA2(c2[3][0], aa3, b01.x); FMA2(c2[3][1], aa3, b01.y);
        FMA2(c2[3][2], aa3, b23.x); FMA2(c2[3][3], aa3, b23.y);
        FMA2(psd[3], aa3, a12);
    }
#pragma unroll
    for (int i = 0; i < 4; i++) {
        int grow = row0 + r0 + i;
        if (grow < N_NODES) {
            float2 p0 = up2(c2[i][0]), p1 = up2(c2[i][1]), p2 = up2(c2[i][2]), p3 = up2(c2[i][3]);
            float4 o0 = make_float4(p0.x + sb[c0], p0.y + sb[c0 + 1],
                                    p1.x + sb[c0 + 2], p1.y + sb[c0 + 3]);
            float4 o1 = make_float4(p2.x + sb[c0 + 4], p2.y + sb[c0 + 5],
                                    p3.x + sb[c0 + 6], p3.y + sb[c0 + 7]);
            *(float4*)(g_msg + (size_t)grow * H + c0) = o0;
            *(float4*)(g_msg + (size_t)grow * H + c0 + 4) = o1;
            if (ct == 0) {
                float2 pv = up2(psd[i]);
                g_ps[grow] = pv.x;
                g_pd[grow] = pv.y;
            }
        }
    }
}

// ---------------- layer edge: softmax + aggregate + clip(relu) ----------------
__global__ void __launch_bounds__(256) k_layer_edge(int l, int last, float* __restrict__ out_h) {
    __shared__ float spte[NT];
    __shared__ float sEx[8][128];
    __shared__ unsigned int sPk[8][128];
    if (threadIdx.x < NT) spte[threadIdx.x] = g_pte[l * NT + threadIdx.x];
    __syncthreads();
    int w = threadIdx.x >> 5, lane = threadIdx.x & 31;
    int d = blockIdx.x * 8 + w;
    if (d >= N_NODES) return;
    int row0 = g_rowptr[d];
    int deg = g_rowptr[d + 1] - row0;
    int sub = lane & 15, half = lane >> 4;
    float4 acc = make_float4(0.f, 0.f, 0.f, 0.f);
    if (deg > 0 && deg <= 128) {
        float pdv = g_pd[d];
        float s_reg[4];
        float smax = -1e30f;
#pragma unroll
        for (int c = 0; c < 4; c++) {
            int i = lane + 32 * c;
            if (i < deg) {
                unsigned int p = g_pack[row0 + i];
                float s = g_ps[p & 0xffffu] + pdv + spte[p >> 16];
                s = s > 0.f ? s : 0.2f * s;
                sPk[w][i] = p;
                s_reg[c] = s;
                smax = fmaxf(smax, s);
            }
        }
#pragma unroll
        for (int o = 16; o; o >>= 1) smax = fmaxf(smax, __shfl_xor_sync(0xffffffffu, smax, o));
        float den = 0.f;
#pragma unroll
        for (int c = 0; c < 4; c++) {
            int i = lane + 32 * c;
            if (i < deg) {
                float ex = expf(s_reg[c] - smax);
                sEx[w][i] = ex;
                den += ex;
            }
        }
        den = warpReduceSum(den);
        float inv = 1.f / (den + EPSF);
        __syncwarp();
        for (int j2 = 0; j2 < deg; j2 += 2) {
            int jh = j2 + half;
            if (jh < deg) {
                float wgt = sEx[w][jh] * inv;
                unsigned int p = sPk[w][jh];
                int sn = p & 0xffffu;
                float4 m = ((const float4*)(g_msg + (size_t)sn * H))[sub];
                acc.x = fmaf(wgt, m.x, acc.x);
                acc.y = fmaf(wgt, m.y, acc.y);
                acc.z = fmaf(wgt, m.z, acc.z);
                acc.w = fmaf(wgt, m.w, acc.w);
            }
        }
    } else if (deg > 128) {
        // rare slow path: fully global
        float pdv = g_pd[d];
        float smax = -1e30f;
        for (int i = lane; i < deg; i += 32) {
            unsigned int p = g_pack[row0 + i];
            float s = g_ps[p & 0xffffu] + pdv + spte[p >> 16];
            s = s > 0.f ? s : 0.2f * s;
            g_ex[row0 + i] = s;
            smax = fmaxf(smax, s);
        }
#pragma unroll
        for (int o = 16; o; o >>= 1) smax = fmaxf(smax, __shfl_xor_sync(0xffffffffu, smax, o));
        float den = 0.f;
        for (int i = lane; i < deg; i += 32) {
            float ex = expf(g_ex[row0 + i] - smax);
            g_ex[row0 + i] = ex;
            den += ex;
        }
        den = warpReduceSum(den);
        float inv = 1.f / (den + EPSF);
        __syncwarp();
        for (int j2 = 0; j2 < deg; j2 += 2) {
            int jh = j2 + half;
            if (jh < deg) {
                float wgt = g_ex[row0 + jh] * inv;
                unsigned int p = g_pack[row0 + jh];
                int sn = p & 0xffffu;
                float4 m = ((const float4*)(g_msg + (size_t)sn * H))[sub];
                acc.x = fmaf(wgt, m.x, acc.x);
                acc.y = fmaf(wgt, m.y, acc.y);
                acc.z = fmaf(wgt, m.z, acc.z);
                acc.w = fmaf(wgt, m.w, acc.w);
            }
        }
    }
    // combine halves
    acc.x += __shfl_xor_sync(0xffffffffu, acc.x, 16);
    acc.y += __shfl_xor_sync(0xffffffffu, acc.y, 16);
    acc.z += __shfl_xor_sync(0xffffffffu, acc.z, 16);
    acc.w += __shfl_xor_sync(0xffffffffu, acc.w, 16);
    // relu + norm + clip
    float u0 = fmaxf(acc.x, 0.f), u1 = fmaxf(acc.y, 0.f);
    float u2 = fmaxf(acc.z, 0.f), u3 = fmaxf(acc.w, 0.f);
    float nn = u0 * u0 + u1 * u1 + u2 * u2 + u3 * u3;
#pragma unroll
    for (int o = 8; o; o >>= 1) nn += __shfl_xor_sync(0xffffffffu, nn, o, 16);
    float n = fmaxf(sqrtf(nn), EPSF);
    float th = tanhf(n);
    float fac = (th < 1.f - 1e-5f) ? 1.f : ATANH_CLIP / n;
    if (half == 0) {
        ((float4*)(g_ht + (size_t)d * H))[sub] =
            make_float4(u0 * fac, u1 * fac, u2 * fac, u3 * fac);
        if (last) {
            float fh = th / n;
            ((float4*)(out_h + (size_t)d * H))[sub] =
                make_float4(u0 * fh, u1 * fh, u2 * fh, u3 * fh);
        }
    }
}

// ---------------- final node: 3 GEMMs from ht_final ----------------
__global__ void __launch_bounds__(128) k_final_node(const float* __restrict__ Wns1,
                                                    const float* __restrict__ Wns2,
                                                    const float* __restrict__ bns2,
                                                    const float* __restrict__ Wes1,
                                                    float* __restrict__ out_ns) {
    __shared__ __align__(16) float2 sA2[64 * 66];
    __shared__ __align__(16) float sB[64 * 64];
    __shared__ float sqb[64], sw2[64];
    int tid = threadIdx.x;
    int row0 = blockIdx.x * 64;
    if (tid < 64) {
        sqb[tid] = g_qbn[tid];
        sw2[tid] = Wns2[tid];
    }
    load_A64_dup(g_ht, H, row0, 0, sA2);
    int rt = tid >> 3, ct = tid & 7;
    int r0 = rt * 4, c0 = ct * 8;
    const float* Wp[3] = {Wns1, Wes1, Wes1 + 64 * 64};
#pragma unroll
    for (int ph = 0; ph < 3; ph++) {
        __syncthreads();
        load_B64(Wp[ph], sB);
        __syncthreads();
        unsigned long long c2[4][4];
        ZERO_C2(c2);
        gemm_frag2(sA2, sB, r0, c0, c2);
        if (ph == 0) {
#pragma unroll
            for (int i = 0; i < 4; i++) {
                float2 p0 = up2(c2[i][0]), p1 = up2(c2[i][1]), p2 = up2(c2[i][2]), p3 = up2(c2[i][3]);
                float cv[8] = {p0.x, p0.y, p1.x, p1.y, p2.x, p2.y, p3.x, p3.y};
                float dot = 0.f;
#pragma unroll
                for (int j = 0; j < 8; j++) {
                    float hn = fmaxf(cv[j] + sqb[c0 + j], 0.f);
                    dot = fmaf(hn, sw2[c0 + j], dot);
                }
                dot = red8(dot);
                int grow = row0 + r0 + i;
                if (ct == 0 && grow < N_NODES) {
                    float lg = dot + bns2[0];
                    out_ns[grow] = 1.f / (1.f + expf(-lg));
                }
            }
        } else {
            float* dstp = (ph == 1) ? g_A : g_B;
#pragma unroll
            for (int i = 0; i < 4; i++) {
                int grow = row0 + r0 + i;
                if (grow < N_NODES) {
                    float2 p0 = up2(c2[i][0]), p1 = up2(c2[i][1]), p2 = up2(c2[i][2]), p3 = up2(c2[i][3]);
                    *(float4*)(dstp + (size_t)grow * H + c0) = make_float4(p0.x, p0.y, p1.x, p1.y);
                    *(float4*)(dstp + (size_t)grow * H + c0 + 4) = make_float4(p2.x, p2.y, p3.x, p3.y);
                }
            }
        }
    }
}

// ---------------- final edge scores (CSR order, warp per dst) ----------------
__global__ void __launch_bounds__(256) k_final_edge(const float* __restrict__ Wes2,
                                                    const float* __restrict__ bes2,
                                                    float* __restrict__ out_es) {
    __shared__ __align__(16) float sC[NT * H];  // teC + qbe folded
    __shared__ __align__(16) float sW2[H];
    for (int i = threadIdx.x; i < NT * H; i += 256) sC[i] = g_teC[i];
    if (threadIdx.x < H) sW2[threadIdx.x] = Wes2[threadIdx.x];
    __syncthreads();
    int w = threadIdx.x >> 5, lane = threadIdx.x & 31;
    int d = blockIdx.x * 8 + w;
    if (d >= N_NODES) return;
    int row0 = g_rowptr[d];
    int deg = g_rowptr[d + 1] - row0;
    if (deg == 0) return;
    int sub = lane & 15, half = lane >> 4;
    float4 b = ((const float4*)(g_B + (size_t)d * H))[sub];
    float4 w2 = ((const float4*)sW2)[sub];
    float bias = bes2[0];
    for (int j2 = 0; j2 < deg; j2 += 2) {
        int jh = j2 + half;
        bool v = jh < deg;
        float dot = 0.f;
        int eo = 0;
        if (v) {
            int j = row0 + jh;
            unsigned int p = g_pack[j];
            eo = g_eord[j];
            int sn = p & 0xffffu, t = p >> 16;
            float4 a = ((const float4*)(g_A + (size_t)sn * H))[sub];
            float4 cte = ((const float4*)(sC + t * H))[sub];
            float h0 = fmaxf(a.x + b.x + cte.x, 0.f);
            float h1 = fmaxf(a.y + b.y + cte.y, 0.f);
            float h2 = fmaxf(a.z + b.z + cte.z, 0.f);
            float h3 = fmaxf(a.w + b.w + cte.w, 0.f);
            dot = h0 * w2.x + h1 * w2.y + h2 * w2.z + h3 * w2.w;
        }
#pragma unroll
        for (int o = 8; o; o >>= 1) dot += __shfl_xor_sync(0xffffffffu, dot, o, 16);
        if (v && sub == 0) {
            float lg = dot + bias;
            out_es[eo] = 1.f / (1.f + expf(-lg));
        }
    }
}

// ---------------- launch ----------------
extern "C" void kernel_launch(void* const* d_in, const int* in_sizes, int n_in,
                              void* d_out, int out_size) {
    const float* nf    = (const float*)d_in[0];
    const float* edesc = (const float*)d_in[1];
    const float* query = (const float*)d_in[2];
    const float* Wn    = (const float*)d_in[3];
    const float* bn    = (const float*)d_in[4];
    const float* ts    = (const float*)d_in[5];
    const float* Wq    = (const float*)d_in[6];
    const float* bq    = (const float*)d_in[7];
    const float* Ws    = (const float*)d_in[8];
    const float* bs    = (const float*)d_in[9];
    const float* attn  = (const float*)d_in[10];
    const float* Wmp   = (const float*)d_in[11];
    const float* bmp   = (const float*)d_in[12];
    const float* Wns1  = (const float*)d_in[13];
    const float* bns1  = (const float*)d_in[14];
    const float* Wns2  = (const float*)d_in[15];
    const float* bns2  = (const float*)d_in[16];
    const float* Wes1  = (const float*)d_in[17];
    const float* bes1  = (const float*)d_in[18];
    const float* Wes2  = (const float*)d_in[19];
    const float* bes2  = (const float*)d_in[20];
    const int* eidx    = (const int*)d_in[21];
    const int* etype   = (const int*)d_in[22];
    const int* src = eidx;
    const int* dst = eidx + N_EDGES;

    float* out_ns = (float*)d_out;
    float* out_es = out_ns + N_NODES;
    float* out_h  = out_es + N_EDGES;
    float* out_te = out_h + (size_t)N_NODES * H;

    const int NB64        = (N_NODES + 63) / 64;      // 782
    const int NODE_BLOCKS = (N_NODES + 7) / 8;        // 6250
    const int EDGE_BLOCKS = (N_EDGES + 255) / 256;    // 3125
    const int ZERO_BLOCKS = (N_NODES + 255) / 256;
    const int SCAN_BLOCKS = (N_NODES + 1023) / 1024;  // 49

    k_consts<<<1, 256>>>(query, Wq, bq, edesc, Ws, bs, attn, Wns1, bns1, Wes1, bes1, out_te);
    k_zero<<<ZERO_BLOCKS, 256>>>();
    k_hist<<<EDGE_BLOCKS, 256>>>(dst);
    k_scan_part<<<SCAN_BLOCKS, 1024>>>();
    k_scan_top<<<1, 64>>>(SCAN_BLOCKS);
    k_scan_add<<<SCAN_BLOCKS, 1024>>>();
    k_fill<<<EDGE_BLOCKS, 256>>>(src, dst, etype);

    k_embed<<<NB64, 128>>>(nf, Wn, bn, ts);

    for (int l = 0; l < NLAYERS; l++) {
        k_msg<<<NB64, 128>>>(Wmp + (size_t)l * H * H, bmp + l * H, attn + l * (2 * H + TD));
        k_layer_edge<<<NODE_BLOCKS, 256>>>(l, (l == NLAYERS - 1) ? 1 : 0, out_h);
    }

    k_final_node<<<NB64, 128>>>(Wns1, Wns2, bns2, Wes1, out_ns);
    k_final_edge<<<NODE_BLOCKS, 256>>>(Wes2, bes2, out_es);
}